// round 12
// baseline (speedup 1.0000x reference)
#include <cuda_runtime.h>

// Problem constants (fixed by the dataset)
#define Nn   50000
#define Ee   800000
#define Gg   512
#define DINc 128

typedef unsigned long long ull;

// ---------- f32x2 packed-FMA helpers (sm_103a) ----------
__device__ __forceinline__ ull fma2(ull a, ull b, ull c) {
    ull d;
    asm("fma.rn.f32x2 %0, %1, %2, %3;" : "=l"(d) : "l"(a), "l"(b), "l"(c));
    return d;
}
__device__ __forceinline__ ull pack2(float x, float y) {
    ull r;
    asm("mov.b64 %0, {%1,%2};" : "=l"(r) : "f"(x), "f"(y));
    return r;
}
__device__ __forceinline__ float2 unpack2(ull v) {
    float2 r;
    asm("mov.b64 {%0,%1}, %2;" : "=f"(r.x), "=f"(r.y) : "l"(v));
    return r;
}
__device__ __forceinline__ float sigmoidf_fast(float x) {
    return __fdividef(1.0f, 1.0f + __expf(-x));
}

// ALL FOUR per-layer edge weight matrices in constant memory (exactly 64 KB).
// Matvec reads are warp-uniform -> LDCU on the uniform port.
__constant__ float cWc[4][4096];

// ---------- scratch (static device globals; row-major e/z) ----------
__device__ float  g_h [(size_t)Nn * 64];
__device__ float  g_e [(size_t)Ee * 64];
__device__ float  g_z [(size_t)Ee * 64];   // holds pre (after mv), then z (after gt)
__device__ float  g_Ah[(size_t)Nn * 64];
__device__ float  g_Bh[(size_t)Nn * 64];
__device__ float  g_Dh[(size_t)Nn * 64];
__device__ float  g_Eh[(size_t)Nn * 64];
__device__ float  g_num[(size_t)Nn * 64];
__device__ float  g_den[(size_t)Nn * 64];
__device__ float  g_hn[(size_t)Nn * 64];
__device__ double g_statsP[32][256];   // striped: [0:64) e_sum [64:128) e_sq [128:192) h_sum [192:256) h_sq
__device__ __align__(16) float g_bnp[256];  // [0:64) mu_e [64:128) inv_e [128:192) mu_h [192:256) inv_h
__device__ float  g_cnt[Gg];

// ---------- initial node embedding: h = nodes_feat @ W_h + b_h ----------
__global__ void __launch_bounds__(256) k_embed_h(const float* __restrict__ x,
                                                 const float* __restrict__ W,
                                                 const float* __restrict__ b) {
    __shared__ __align__(16) float sW[DINc][64];
    __shared__ __align__(16) float sx[16][DINc];
    const int t = threadIdx.x;
    for (int i = t; i < DINc * 64 / 4; i += 256)
        ((float4*)&sW[0][0])[i] = ((const float4*)W)[i];

    const int cq = t & 15, m = t >> 4;
    const float4 bias = ((const float4*)b)[cq];
    const int base = blockIdx.x * 64;

    for (int it = 0; it < 4; it++) {
        const int n0 = base + it * 16;
        __syncthreads();
        for (int i = t; i < 16 * DINc / 4; i += 256) {
            const int row = i >> 5, c4 = i & 31;
            const int n = n0 + row;
            float4 v = make_float4(0.f, 0.f, 0.f, 0.f);
            if (n < Nn) v = ((const float4*)x)[(size_t)n * 32 + c4];
            ((float4*)&sx[row][0])[c4] = v;
        }
        __syncthreads();
        float4 acc = bias;
        #pragma unroll 8
        for (int k = 0; k < DINc; k++) {
            const float xv = sx[m][k];
            const float4 w = ((const float4*)&sW[k][0])[cq];
            acc.x += xv * w.x; acc.y += xv * w.y;
            acc.z += xv * w.z; acc.w += xv * w.w;
        }
        const int n = n0 + m;
        if (n < Nn) ((float4*)g_h)[(size_t)n * 16 + cq] = acc;
    }
}

// ---------- per-layer node GEMMs v3: 4 nodes/thread, f32x2 FMA ----------
extern __shared__ float dsm[];
__global__ void __launch_bounds__(256, 2) k_node_gemm(
        const float* __restrict__ Wa, const float* __restrict__ Wb,
        const float* __restrict__ Wd, const float* __restrict__ We_,
        const float* __restrict__ ba_, const float* __restrict__ bb_,
        const float* __restrict__ bd_, const float* __restrict__ be_) {
    float* sW = dsm;              // 4 * 4096 floats
    float* sx = dsm + 4 * 4096;   // 64 * 64 floats
    const int t = threadIdx.x;

    if (blockIdx.x == 0) {        // zero striped BN stats for this layer
        double* p = &g_statsP[0][0];
        for (int i = t; i < 32 * 256; i += 256) p[i] = 0.0;
    }

    for (int i = t; i < 1024; i += 256) ((float4*)(sW + 0 * 4096))[i] = ((const float4*)Wa)[i];
    for (int i = t; i < 1024; i += 256) ((float4*)(sW + 1 * 4096))[i] = ((const float4*)Wb)[i];
    for (int i = t; i < 1024; i += 256) ((float4*)(sW + 2 * 4096))[i] = ((const float4*)Wd)[i];
    for (int i = t; i < 1024; i += 256) ((float4*)(sW + 3 * 4096))[i] = ((const float4*)We_)[i];

    const int cq = t & 15, m = t >> 4;   // thread: nodes 4m..4m+3 of the tile, channels 4cq..4cq+3
    const float4 bA = ((const float4*)ba_)[cq];
    const float4 bB = ((const float4*)bb_)[cq];
    const float4 bD = ((const float4*)bd_)[cq];
    const float4 bE = ((const float4*)be_)[cq];
    const ull bA0 = pack2(bA.x, bA.y), bA1 = pack2(bA.z, bA.w);
    const ull bB0 = pack2(bB.x, bB.y), bB1 = pack2(bB.z, bB.w);
    const ull bD0 = pack2(bD.x, bD.y), bD1 = pack2(bD.z, bD.w);
    const ull bE0 = pack2(bE.x, bE.y), bE1 = pack2(bE.z, bE.w);
    const int base = blockIdx.x * 256;

    for (int it = 0; it < 4; it++) {
        const int n0 = base + it * 64;
        __syncthreads();
        #pragma unroll
        for (int i = t; i < 1024; i += 256) {   // 64 rows x 16 quads
            const int row = i >> 4, c4 = i & 15;
            const int n = n0 + row;
            float4 v = make_float4(0.f, 0.f, 0.f, 0.f);
            if (n < Nn) v = ((const float4*)g_h)[(size_t)n * 16 + c4];
            ((float4*)sx)[row * 16 + c4] = v;
        }
        __syncthreads();
        ull aA[8], aB[8], aD[8], aE[8];   // 4 nodes x 2 channel-pairs
        #pragma unroll
        for (int r = 0; r < 4; r++) {
            aA[2 * r] = bA0; aA[2 * r + 1] = bA1;
            aB[2 * r] = bB0; aB[2 * r + 1] = bB1;
            aD[2 * r] = bD0; aD[2 * r + 1] = bD1;
            aE[2 * r] = bE0; aE[2 * r + 1] = bE1;
        }
        #pragma unroll 4
        for (int k = 0; k < 64; k++) {
            ull x[4];
            #pragma unroll
            for (int r = 0; r < 4; r++) {
                const float xv = sx[(4 * m + r) * 64 + k];
                x[r] = pack2(xv, xv);
            }
            const ull wA0 = ((const ull*)(sW + 0 * 4096 + k * 64))[2 * cq];
            const ull wA1 = ((const ull*)(sW + 0 * 4096 + k * 64))[2 * cq + 1];
            const ull wB0 = ((const ull*)(sW + 1 * 4096 + k * 64))[2 * cq];
            const ull wB1 = ((const ull*)(sW + 1 * 4096 + k * 64))[2 * cq + 1];
            const ull wD0 = ((const ull*)(sW + 2 * 4096 + k * 64))[2 * cq];
            const ull wD1 = ((const ull*)(sW + 2 * 4096 + k * 64))[2 * cq + 1];
            const ull wE0 = ((const ull*)(sW + 3 * 4096 + k * 64))[2 * cq];
            const ull wE1 = ((const ull*)(sW + 3 * 4096 + k * 64))[2 * cq + 1];
            #pragma unroll
            for (int r = 0; r < 4; r++) {
                aA[2 * r] = fma2(x[r], wA0, aA[2 * r]);
                aA[2 * r + 1] = fma2(x[r], wA1, aA[2 * r + 1]);
                aB[2 * r] = fma2(x[r], wB0, aB[2 * r]);
                aB[2 * r + 1] = fma2(x[r], wB1, aB[2 * r + 1]);
                aD[2 * r] = fma2(x[r], wD0, aD[2 * r]);
                aD[2 * r + 1] = fma2(x[r], wD1, aD[2 * r + 1]);
                aE[2 * r] = fma2(x[r], wE0, aE[2 * r]);
                aE[2 * r + 1] = fma2(x[r], wE1, aE[2 * r + 1]);
            }
        }
        #pragma unroll
        for (int r = 0; r < 4; r++) {
            const int n = n0 + 4 * m + r;
            if (n < Nn) {
                const size_t o = (size_t)n * 16 + cq;
                float2 p0, p1;
                p0 = unpack2(aA[2 * r]); p1 = unpack2(aA[2 * r + 1]);
                ((float4*)g_Ah)[o] = make_float4(p0.x, p0.y, p1.x, p1.y);
                p0 = unpack2(aB[2 * r]); p1 = unpack2(aB[2 * r + 1]);
                ((float4*)g_Bh)[o] = make_float4(p0.x, p0.y, p1.x, p1.y);
                p0 = unpack2(aD[2 * r]); p1 = unpack2(aD[2 * r + 1]);
                ((float4*)g_Dh)[o] = make_float4(p0.x, p0.y, p1.x, p1.y);
                p0 = unpack2(aE[2 * r]); p1 = unpack2(aE[2 * r + 1]);
                ((float4*)g_Eh)[o] = make_float4(p0.x, p0.y, p1.x, p1.y);
                ((float4*)g_num)[o] = make_float4(0.f, 0.f, 0.f, 0.f);
                ((float4*)g_den)[o] = make_float4(0.f, 0.f, 0.f, 0.f);
            }
        }
    }
}

// ---------- edge matvec kernel (STREAMING, no gathers): pre = e@Wc + bc -> g_z ----------
// MODE 0 (l=0): e built inline from scalar ef (no e I/O)
// MODE 1 (l>0): read e from g_e
template<int MODE>
__global__ void __launch_bounds__(256) k_edge_mv(
        int layer,
        const float* __restrict__ bc_l,
        const float* __restrict__ ef,
        const float* __restrict__ We_, const float* __restrict__ be_) {
    const int t = blockIdx.x * 256 + threadIdx.x;   // edge id (800000 % 256 == 0)

    ull acc[32];
    #pragma unroll
    for (int q = 0; q < 16; q++) {
        const float4 bv = ((const float4*)bc_l)[q];
        acc[2 * q]     = pack2(bv.x, bv.y);
        acc[2 * q + 1] = pack2(bv.z, bv.w);
    }

    const float f = (MODE == 0) ? ef[t] : 0.f;
    const float4* e4 = ((const float4*)g_e) + (size_t)t * 16;
    const ull* W2 = (const ull*)cWc[layer];   // warp-uniform constant reads (LDCU)

    #pragma unroll 2
    for (int q = 0; q < 16; q++) {
        float4 e_q;
        if (MODE == 0) {
            const float4 w = ((const float4*)We_)[q];
            const float4 b = ((const float4*)be_)[q];
            e_q = make_float4(fmaf(f, w.x, b.x), fmaf(f, w.y, b.y),
                              fmaf(f, w.z, b.z), fmaf(f, w.w, b.w));
        } else {
            e_q = e4[q];
        }
        #pragma unroll
        for (int kk = 0; kk < 4; kk++) {
            const float ek = (kk == 0) ? e_q.x : (kk == 1) ? e_q.y : (kk == 2) ? e_q.z : e_q.w;
            const ull e2 = pack2(ek, ek);
            const ull* w = W2 + (q * 4 + kk) * 32;
            #pragma unroll
            for (int j = 0; j < 32; j++) acc[j] = fma2(e2, w[j], acc[j]);
        }
    }

    float4* pre4 = ((float4*)g_z) + (size_t)t * 16;
    #pragma unroll
    for (int q = 0; q < 16; q++) {
        const float2 a0 = unpack2(acc[2 * q]);
        const float2 a1 = unpack2(acc[2 * q + 1]);
        pre4[q] = make_float4(a0.x, a0.y, a1.x, a1.y);
    }
}

// ---------- edge gather kernel (HIGH OCCUPANCY): a = pre + Dh[s] + Eh[d]; gate; atomics ----------
// WRST 1 (l<3): z = a*enorm written in place over pre; fused BN stats
// WRST 0 (l=3): no z write, no stats
template<int WRST>
__global__ void __launch_bounds__(256, 4) k_edge_gt(
        const int* __restrict__ src, const int* __restrict__ dst,
        const float* __restrict__ enorm) {
    __shared__ float sSum[8][64], sSq[8][64];
    const int t = blockIdx.x * 256 + threadIdx.x;
    const int s = src[t], d = dst[t];
    const float zn = enorm[t];
    const int lane = threadIdx.x & 31, wid = threadIdx.x >> 5;

    float4* pre4 = ((float4*)g_z) + (size_t)t * 16;
    const float4* D4 = ((const float4*)g_Dh) + (size_t)s * 16;
    const float4* E4 = ((const float4*)g_Eh) + (size_t)d * 16;
    const float4* B4 = ((const float4*)g_Bh) + (size_t)s * 16;
    float4* num4 = ((float4*)g_num) + (size_t)d * 16;
    float4* den4 = ((float4*)g_den) + (size_t)d * 16;

    #pragma unroll 4
    for (int q = 0; q < 16; q++) {
        const float4 pv = pre4[q];
        const float4 dv = D4[q];
        const float4 ev = E4[q];
        float4 a;
        a.x = pv.x + dv.x + ev.x; a.y = pv.y + dv.y + ev.y;
        a.z = pv.z + dv.z + ev.z; a.w = pv.w + dv.w + ev.w;
        float4 sg;
        sg.x = sigmoidf_fast(a.x); sg.y = sigmoidf_fast(a.y);
        sg.z = sigmoidf_fast(a.z); sg.w = sigmoidf_fast(a.w);
        if (WRST) {
            const float4 zq = make_float4(a.x * zn, a.y * zn, a.z * zn, a.w * zn);
            pre4[q] = zq;   // z overwrites pre in place
            float s0 = zq.x, s1 = zq.y, s2 = zq.z, s3 = zq.w;
            float q0 = s0 * s0, q1 = s1 * s1, q2 = s2 * s2, q3 = s3 * s3;
            #pragma unroll
            for (int off = 16; off; off >>= 1) {
                s0 += __shfl_xor_sync(0xffffffffu, s0, off);
                s1 += __shfl_xor_sync(0xffffffffu, s1, off);
                s2 += __shfl_xor_sync(0xffffffffu, s2, off);
                s3 += __shfl_xor_sync(0xffffffffu, s3, off);
                q0 += __shfl_xor_sync(0xffffffffu, q0, off);
                q1 += __shfl_xor_sync(0xffffffffu, q1, off);
                q2 += __shfl_xor_sync(0xffffffffu, q2, off);
                q3 += __shfl_xor_sync(0xffffffffu, q3, off);
            }
            if (lane == 0) {
                sSum[wid][4 * q + 0] = s0; sSum[wid][4 * q + 1] = s1;
                sSum[wid][4 * q + 2] = s2; sSum[wid][4 * q + 3] = s3;
                sSq [wid][4 * q + 0] = q0; sSq [wid][4 * q + 1] = q1;
                sSq [wid][4 * q + 2] = q2; sSq [wid][4 * q + 3] = q3;
            }
        }
        const float4 bq = B4[q];
        atomicAdd(&num4[q], make_float4(sg.x * bq.x, sg.y * bq.y, sg.z * bq.z, sg.w * bq.w));
        atomicAdd(&den4[q], sg);
    }

    if (WRST) {
        __syncthreads();
        if (threadIdx.x < 128) {
            const int c = threadIdx.x & 63, part = threadIdx.x >> 6;
            float v = 0.f;
            #pragma unroll
            for (int w = 0; w < 8; w++)
                v += part ? sSq[w][c] : sSum[w][c];
            atomicAdd(&g_statsP[blockIdx.x & 31][part * 64 + c], (double)v);
        }
    }
}

// ---------- streaming edge update (full-BW pass): e_out = base + relu(BN(z)) ----------
// FIRST=1 (l=0): base = embed(ef)
template<int FIRST>
__global__ void __launch_bounds__(256) k_edge_C(
        const float* __restrict__ ef,
        const float* __restrict__ We_, const float* __restrict__ be_,
        const float* __restrict__ gam, const float* __restrict__ bet) {
    const size_t i = (size_t)blockIdx.x * 256 + threadIdx.x;   // quad idx, Ee*16 exact
    if (i >= (size_t)Ee * 16) return;
    const int q = (int)(i & 15);
    const float4 zv = ((const float4*)g_z)[i];
    float4 base;
    if (FIRST) {
        const float f = ef[i >> 4];
        const float4 w = ((const float4*)We_)[q];
        const float4 b = ((const float4*)be_)[q];
        base = make_float4(fmaf(f, w.x, b.x), fmaf(f, w.y, b.y),
                           fmaf(f, w.z, b.z), fmaf(f, w.w, b.w));
    } else {
        base = ((const float4*)g_e)[i];
    }
    const float4 g4 = ((const float4*)gam)[q];
    const float4 b4 = ((const float4*)bet)[q];
    const float4 mu = ((const float4*)g_bnp)[q];
    const float4 iv = ((const float4*)(g_bnp + 64))[q];
    base.x += fmaxf(0.f, g4.x * (zv.x - mu.x) * iv.x + b4.x);
    base.y += fmaxf(0.f, g4.y * (zv.y - mu.y) * iv.y + b4.y);
    base.z += fmaxf(0.f, g4.z * (zv.z - mu.z) * iv.z + b4.z);
    base.w += fmaxf(0.f, g4.w * (zv.w - mu.w) * iv.w + b4.w);
    ((float4*)g_e)[i] = base;
}

// ---------- node aggregate + graph norm + BN stats over hn ----------
__global__ void __launch_bounds__(256) k_node_B(const float* __restrict__ nnorm) {
    const int c = threadIdx.x & 63;
    const int slot = threadIdx.x >> 6;
    double s = 0.0, q = 0.0;
    for (int n = blockIdx.x * 4 + slot; n < Nn; n += gridDim.x * 4) {
        const size_t idx = (size_t)n * 64 + c;
        const float v = (g_Ah[idx] + g_num[idx] / (g_den[idx] + 1e-6f)) * nnorm[n];
        g_hn[idx] = v;
        s += v;
        q += (double)v * (double)v;
    }
    __shared__ double sh[512];
    sh[threadIdx.x] = s;
    sh[256 + threadIdx.x] = q;
    __syncthreads();
    if (threadIdx.x < 64) {
        s = sh[c] + sh[c + 64] + sh[c + 128] + sh[c + 192];
        q = sh[256 + c] + sh[256 + c + 64] + sh[256 + c + 128] + sh[256 + c + 192];
        const int st = blockIdx.x & 31;
        atomicAdd(&g_statsP[st][128 + c], s);
        atomicAdd(&g_statsP[st][192 + c], q);
    }
}

__global__ void k_finalize() {
    const int c = threadIdx.x;  // 64 threads
    double se = 0.0, qe = 0.0, sh2 = 0.0, qh = 0.0;
    #pragma unroll 4
    for (int st = 0; st < 32; st++) {
        se  += g_statsP[st][c];
        qe  += g_statsP[st][64 + c];
        sh2 += g_statsP[st][128 + c];
        qh  += g_statsP[st][192 + c];
    }
    const double mu_e = se / (double)Ee;
    const double var_e = qe / (double)Ee - mu_e * mu_e;
    g_bnp[c] = (float)mu_e;
    g_bnp[64 + c] = (float)(1.0 / sqrt(var_e + 1e-5));
    const double mu_h = sh2 / (double)Nn;
    const double var_h = qh / (double)Nn - mu_h * mu_h;
    g_bnp[128 + c] = (float)mu_h;
    g_bnp[192 + c] = (float)(1.0 / sqrt(var_h + 1e-5));
}

// ---------- node residual update: h += relu(BN(hn)) ----------
__global__ void __launch_bounds__(256) k_node_C(const float* __restrict__ gam,
                                                const float* __restrict__ bet) {
    const int i = blockIdx.x * 256 + threadIdx.x;
    if (i >= Nn * 16) return;
    const int q = i & 15;
    float4 hv = ((float4*)g_h)[i];
    const float4 hn = ((float4*)g_hn)[i];
    const float4 g4 = ((const float4*)gam)[q];
    const float4 b4 = ((const float4*)bet)[q];
    const float4 mu = ((const float4*)(g_bnp + 128))[q];
    const float4 iv = ((const float4*)(g_bnp + 192))[q];
    hv.x += fmaxf(0.f, g4.x * (hn.x - mu.x) * iv.x + b4.x);
    hv.y += fmaxf(0.f, g4.y * (hn.y - mu.y) * iv.y + b4.y);
    hv.z += fmaxf(0.f, g4.z * (hn.z - mu.z) * iv.z + b4.z);
    hv.w += fmaxf(0.f, g4.w * (hn.w - mu.w) * iv.w + b4.w);
    ((float4*)g_h)[i] = hv;
}

// ---------- readout (fused last-layer node BN+residual) ----------
__global__ void k_zero_out(float* __restrict__ out) {
    const int i = blockIdx.x * 256 + threadIdx.x;   // 128 blocks -> 32768 exact
    out[i] = 0.f;
    if (i < Gg) g_cnt[i] = 0.f;
}

__global__ void __launch_bounds__(256) k_readout(const int* __restrict__ gid,
                                                 const float* __restrict__ gamH,
                                                 const float* __restrict__ betH,
                                                 float* __restrict__ out) {
    const int i = blockIdx.x * 256 + threadIdx.x;   // exact: Nn*16 = 800000
    const int q = i & 15, n = i >> 4;
    float4 hv = ((const float4*)g_h)[i];
    const float4 hn = ((const float4*)g_hn)[i];
    const float4 g4 = ((const float4*)gamH)[q];
    const float4 b4 = ((const float4*)betH)[q];
    const float4 mu = ((const float4*)(g_bnp + 128))[q];
    const float4 iv = ((const float4*)(g_bnp + 192))[q];
    hv.x += fmaxf(0.f, g4.x * (hn.x - mu.x) * iv.x + b4.x);
    hv.y += fmaxf(0.f, g4.y * (hn.y - mu.y) * iv.y + b4.y);
    hv.z += fmaxf(0.f, g4.z * (hn.z - mu.z) * iv.z + b4.z);
    hv.w += fmaxf(0.f, g4.w * (hn.w - mu.w) * iv.w + b4.w);
    const int g = gid[n];
    atomicAdd(((float4*)out) + (size_t)g * 16 + q, hv);
    if (q == 0) atomicAdd(&g_cnt[g], 1.0f);
}

__global__ void k_div(float* __restrict__ out) {
    const int i = blockIdx.x * 256 + threadIdx.x;   // exact 32768
    out[i] /= fmaxf(g_cnt[i >> 6], 1.0f);
}

// =====================================================================
extern "C" void kernel_launch(void* const* d_in, const int* in_sizes, int n_in,
                              void* d_out, int out_size) {
    const float* nodes_feat = (const float*)d_in[0];
    const float* edges_feat = (const float*)d_in[1];
    const float* nnorm      = (const float*)d_in[2];
    const float* enorm      = (const float*)d_in[3];
    const float* W_h        = (const float*)d_in[4];
    const float* b_h        = (const float*)d_in[5];
    const float* W_e        = (const float*)d_in[6];
    const float* b_e        = (const float*)d_in[7];
    const float* Wa         = (const float*)d_in[8];
    const float* ba         = (const float*)d_in[9];
    const float* Wb         = (const float*)d_in[10];
    const float* bb         = (const float*)d_in[11];
    const float* Wc         = (const float*)d_in[12];
    const float* bc         = (const float*)d_in[13];
    const float* Wd         = (const float*)d_in[14];
    const float* bd         = (const float*)d_in[15];
    const float* We         = (const float*)d_in[16];
    const float* be         = (const float*)d_in[17];
    const float* gamma_h    = (const float*)d_in[18];
    const float* beta_h     = (const float*)d_in[19];
    const float* gamma_e    = (const float*)d_in[20];
    const float* beta_e     = (const float*)d_in[21];
    const int*   esrc       = (const int*)d_in[22];
    const int*   edst       = (const int*)d_in[23];
    const int*   gid        = (const int*)d_in[24];
    float* out = (float*)d_out;

    const int dynSmem = 4 * 4096 * 4 + 64 * 64 * 4;   // 81920 bytes
    cudaFuncSetAttribute(k_node_gemm, cudaFuncAttributeMaxDynamicSharedMemorySize, dynSmem);

    // all four Wc layers into constant memory (one 64 KB D2D copy)
    cudaMemcpyToSymbolAsync(cWc, Wc, 4 * 4096 * sizeof(float), 0,
                            cudaMemcpyDeviceToDevice, 0);                   // 1
    k_embed_h<<<(Nn + 63) / 64, 256>>>(nodes_feat, W_h, b_h);               // 2
    k_zero_out<<<128, 256>>>(out);                                          // 3

    const int NG = (Nn + 255) / 256;   // 196 blocks (256 nodes/block)
    const int EG = Ee / 256;           // 3125 blocks, thread-per-edge
    const int EC = (int)(((size_t)Ee * 16 + 255) / 256);
    for (int l = 0; l < 4; l++) {
        k_node_gemm<<<NG, 256, dynSmem>>>(
            Wa + (size_t)l * 4096, Wb + (size_t)l * 4096,
            Wd + (size_t)l * 4096, We + (size_t)l * 4096,
            ba + l * 64, bb + l * 64, bd + l * 64, be + l * 64);            // 4 (l=0)

        const float* bcL = bc + l * 64;
        if (l == 0)
            k_edge_mv<0><<<EG, 256>>>(l, bcL, edges_feat, W_e, b_e);        // 5 <- profiled
        else
            k_edge_mv<1><<<EG, 256>>>(l, bcL, edges_feat, W_e, b_e);

        if (l < 3)
            k_edge_gt<1><<<EG, 256>>>(esrc, edst, enorm);
        else
            k_edge_gt<0><<<EG, 256>>>(esrc, edst, enorm);

        k_node_B<<<1024, 256>>>(nnorm);
        k_finalize<<<1, 64>>>();
        if (l < 3) {
            k_node_C<<<(Nn * 16 + 255) / 256, 256>>>(gamma_h + l * 64, beta_h + l * 64);
            if (l == 0)
                k_edge_C<1><<<EC, 256>>>(edges_feat, W_e, b_e,
                                         gamma_e + l * 64, beta_e + l * 64);
            else
                k_edge_C<0><<<EC, 256>>>(edges_feat, W_e, b_e,
                                         gamma_e + l * 64, beta_e + l * 64);
        }
    }

    k_readout<<<Nn * 16 / 256, 256>>>(gid, gamma_h + 3 * 64, beta_h + 3 * 64, out);
    k_div<<<Gg * 64 / 256, 256>>>(out);
}

// round 13
// speedup vs baseline: 1.3516x; 1.3516x over previous
#include <cuda_runtime.h>

// Problem constants (fixed by the dataset)
#define Nn   50000
#define Ee   800000
#define Gg   512
#define DINc 128

typedef unsigned long long ull;

// ---------- f32x2 packed-FMA helpers (sm_103a) ----------
__device__ __forceinline__ ull fma2(ull a, ull b, ull c) {
    ull d;
    asm("fma.rn.f32x2 %0, %1, %2, %3;" : "=l"(d) : "l"(a), "l"(b), "l"(c));
    return d;
}
__device__ __forceinline__ ull pack2(float x, float y) {
    ull r;
    asm("mov.b64 %0, {%1,%2};" : "=l"(r) : "f"(x), "f"(y));
    return r;
}
__device__ __forceinline__ float2 unpack2(ull v) {
    float2 r;
    asm("mov.b64 {%0,%1}, %2;" : "=f"(r.x), "=f"(r.y) : "l"(v));
    return r;
}
__device__ __forceinline__ float sigmoidf_fast(float x) {
    return __fdividef(1.0f, 1.0f + __expf(-x));
}

// ALL FOUR per-layer edge weight matrices in constant memory (exactly 64 KB).
// Matvec reads are warp-uniform -> LDCU on the uniform port.
__constant__ float cWc[4][4096];

// ---------- scratch (static device globals; row-major e/z) ----------
__device__ float  g_h [(size_t)Nn * 64];
__device__ float  g_e [(size_t)Ee * 64];
__device__ float  g_z [(size_t)Ee * 64];   // holds pre (after mv), then z (after gt)
__device__ float  g_Ah[(size_t)Nn * 64];
__device__ float  g_Bh[(size_t)Nn * 64];
__device__ float  g_Dh[(size_t)Nn * 64];
__device__ float  g_Eh[(size_t)Nn * 64];
__device__ float  g_num[(size_t)Nn * 64];
__device__ float  g_den[(size_t)Nn * 64];
__device__ float  g_hn[(size_t)Nn * 64];
__device__ double g_statsP[32][256];   // striped: [0:64) e_sum [64:128) e_sq [128:192) h_sum [192:256) h_sq
__device__ __align__(16) float g_bnp[256];  // [0:64) mu_e [64:128) inv_e [128:192) mu_h [192:256) inv_h
__device__ float  g_cnt[Gg];

// ---------- initial node embedding: h = nodes_feat @ W_h + b_h ----------
__global__ void __launch_bounds__(256) k_embed_h(const float* __restrict__ x,
                                                 const float* __restrict__ W,
                                                 const float* __restrict__ b) {
    __shared__ __align__(16) float sW[DINc][64];
    __shared__ __align__(16) float sx[16][DINc];
    const int t = threadIdx.x;
    for (int i = t; i < DINc * 64 / 4; i += 256)
        ((float4*)&sW[0][0])[i] = ((const float4*)W)[i];

    const int cq = t & 15, m = t >> 4;
    const float4 bias = ((const float4*)b)[cq];
    const int base = blockIdx.x * 64;

    for (int it = 0; it < 4; it++) {
        const int n0 = base + it * 16;
        __syncthreads();
        for (int i = t; i < 16 * DINc / 4; i += 256) {
            const int row = i >> 5, c4 = i & 31;
            const int n = n0 + row;
            float4 v = make_float4(0.f, 0.f, 0.f, 0.f);
            if (n < Nn) v = ((const float4*)x)[(size_t)n * 32 + c4];
            ((float4*)&sx[row][0])[c4] = v;
        }
        __syncthreads();
        float4 acc = bias;
        #pragma unroll 8
        for (int k = 0; k < DINc; k++) {
            const float xv = sx[m][k];
            const float4 w = ((const float4*)&sW[k][0])[cq];
            acc.x += xv * w.x; acc.y += xv * w.y;
            acc.z += xv * w.z; acc.w += xv * w.w;
        }
        const int n = n0 + m;
        if (n < Nn) ((float4*)g_h)[(size_t)n * 16 + cq] = acc;
    }
}

// ---------- per-layer node GEMMs v3: 4 nodes/thread, f32x2 FMA ----------
extern __shared__ float dsm[];
__global__ void __launch_bounds__(256, 2) k_node_gemm(
        const float* __restrict__ Wa, const float* __restrict__ Wb,
        const float* __restrict__ Wd, const float* __restrict__ We_,
        const float* __restrict__ ba_, const float* __restrict__ bb_,
        const float* __restrict__ bd_, const float* __restrict__ be_) {
    float* sW = dsm;              // 4 * 4096 floats
    float* sx = dsm + 4 * 4096;   // 64 * 64 floats
    const int t = threadIdx.x;

    if (blockIdx.x == 0) {        // zero striped BN stats for this layer
        double* p = &g_statsP[0][0];
        for (int i = t; i < 32 * 256; i += 256) p[i] = 0.0;
    }

    for (int i = t; i < 1024; i += 256) ((float4*)(sW + 0 * 4096))[i] = ((const float4*)Wa)[i];
    for (int i = t; i < 1024; i += 256) ((float4*)(sW + 1 * 4096))[i] = ((const float4*)Wb)[i];
    for (int i = t; i < 1024; i += 256) ((float4*)(sW + 2 * 4096))[i] = ((const float4*)Wd)[i];
    for (int i = t; i < 1024; i += 256) ((float4*)(sW + 3 * 4096))[i] = ((const float4*)We_)[i];

    const int cq = t & 15, m = t >> 4;   // thread: nodes 4m..4m+3 of the tile, channels 4cq..4cq+3
    const float4 bA = ((const float4*)ba_)[cq];
    const float4 bB = ((const float4*)bb_)[cq];
    const float4 bD = ((const float4*)bd_)[cq];
    const float4 bE = ((const float4*)be_)[cq];
    const ull bA0 = pack2(bA.x, bA.y), bA1 = pack2(bA.z, bA.w);
    const ull bB0 = pack2(bB.x, bB.y), bB1 = pack2(bB.z, bB.w);
    const ull bD0 = pack2(bD.x, bD.y), bD1 = pack2(bD.z, bD.w);
    const ull bE0 = pack2(bE.x, bE.y), bE1 = pack2(bE.z, bE.w);
    const int base = blockIdx.x * 256;

    for (int it = 0; it < 4; it++) {
        const int n0 = base + it * 64;
        __syncthreads();
        #pragma unroll
        for (int i = t; i < 1024; i += 256) {   // 64 rows x 16 quads
            const int row = i >> 4, c4 = i & 15;
            const int n = n0 + row;
            float4 v = make_float4(0.f, 0.f, 0.f, 0.f);
            if (n < Nn) v = ((const float4*)g_h)[(size_t)n * 16 + c4];
            ((float4*)sx)[row * 16 + c4] = v;
        }
        __syncthreads();
        ull aA[8], aB[8], aD[8], aE[8];   // 4 nodes x 2 channel-pairs
        #pragma unroll
        for (int r = 0; r < 4; r++) {
            aA[2 * r] = bA0; aA[2 * r + 1] = bA1;
            aB[2 * r] = bB0; aB[2 * r + 1] = bB1;
            aD[2 * r] = bD0; aD[2 * r + 1] = bD1;
            aE[2 * r] = bE0; aE[2 * r + 1] = bE1;
        }
        #pragma unroll 4
        for (int k = 0; k < 64; k++) {
            ull x[4];
            #pragma unroll
            for (int r = 0; r < 4; r++) {
                const float xv = sx[(4 * m + r) * 64 + k];
                x[r] = pack2(xv, xv);
            }
            const ull wA0 = ((const ull*)(sW + 0 * 4096 + k * 64))[2 * cq];
            const ull wA1 = ((const ull*)(sW + 0 * 4096 + k * 64))[2 * cq + 1];
            const ull wB0 = ((const ull*)(sW + 1 * 4096 + k * 64))[2 * cq];
            const ull wB1 = ((const ull*)(sW + 1 * 4096 + k * 64))[2 * cq + 1];
            const ull wD0 = ((const ull*)(sW + 2 * 4096 + k * 64))[2 * cq];
            const ull wD1 = ((const ull*)(sW + 2 * 4096 + k * 64))[2 * cq + 1];
            const ull wE0 = ((const ull*)(sW + 3 * 4096 + k * 64))[2 * cq];
            const ull wE1 = ((const ull*)(sW + 3 * 4096 + k * 64))[2 * cq + 1];
            #pragma unroll
            for (int r = 0; r < 4; r++) {
                aA[2 * r] = fma2(x[r], wA0, aA[2 * r]);
                aA[2 * r + 1] = fma2(x[r], wA1, aA[2 * r + 1]);
                aB[2 * r] = fma2(x[r], wB0, aB[2 * r]);
                aB[2 * r + 1] = fma2(x[r], wB1, aB[2 * r + 1]);
                aD[2 * r] = fma2(x[r], wD0, aD[2 * r]);
                aD[2 * r + 1] = fma2(x[r], wD1, aD[2 * r + 1]);
                aE[2 * r] = fma2(x[r], wE0, aE[2 * r]);
                aE[2 * r + 1] = fma2(x[r], wE1, aE[2 * r + 1]);
            }
        }
        #pragma unroll
        for (int r = 0; r < 4; r++) {
            const int n = n0 + 4 * m + r;
            if (n < Nn) {
                const size_t o = (size_t)n * 16 + cq;
                float2 p0, p1;
                p0 = unpack2(aA[2 * r]); p1 = unpack2(aA[2 * r + 1]);
                ((float4*)g_Ah)[o] = make_float4(p0.x, p0.y, p1.x, p1.y);
                p0 = unpack2(aB[2 * r]); p1 = unpack2(aB[2 * r + 1]);
                ((float4*)g_Bh)[o] = make_float4(p0.x, p0.y, p1.x, p1.y);
                p0 = unpack2(aD[2 * r]); p1 = unpack2(aD[2 * r + 1]);
                ((float4*)g_Dh)[o] = make_float4(p0.x, p0.y, p1.x, p1.y);
                p0 = unpack2(aE[2 * r]); p1 = unpack2(aE[2 * r + 1]);
                ((float4*)g_Eh)[o] = make_float4(p0.x, p0.y, p1.x, p1.y);
                ((float4*)g_num)[o] = make_float4(0.f, 0.f, 0.f, 0.f);
                ((float4*)g_den)[o] = make_float4(0.f, 0.f, 0.f, 0.f);
            }
        }
    }
}

// ---------- edge matvec kernel (STREAMING, no gathers): pre = e@Wc + bc -> g_z ----------
// MODE 0 (l=0): e built inline from scalar ef (no e I/O)
// MODE 1 (l>0): read e from g_e
template<int MODE>
__global__ void __launch_bounds__(256) k_edge_mv(
        int layer,
        const float* __restrict__ bc_l,
        const float* __restrict__ ef,
        const float* __restrict__ We_, const float* __restrict__ be_) {
    const int t = blockIdx.x * 256 + threadIdx.x;   // edge id (800000 % 256 == 0)

    ull acc[32];
    #pragma unroll
    for (int q = 0; q < 16; q++) {
        const float4 bv = ((const float4*)bc_l)[q];
        acc[2 * q]     = pack2(bv.x, bv.y);
        acc[2 * q + 1] = pack2(bv.z, bv.w);
    }

    const float f = (MODE == 0) ? ef[t] : 0.f;
    const float4* e4 = ((const float4*)g_e) + (size_t)t * 16;
    const ull* W2 = (const ull*)cWc[layer];   // warp-uniform constant reads (LDCU)

    #pragma unroll 2
    for (int q = 0; q < 16; q++) {
        float4 e_q;
        if (MODE == 0) {
            const float4 w = ((const float4*)We_)[q];
            const float4 b = ((const float4*)be_)[q];
            e_q = make_float4(fmaf(f, w.x, b.x), fmaf(f, w.y, b.y),
                              fmaf(f, w.z, b.z), fmaf(f, w.w, b.w));
        } else {
            e_q = e4[q];
        }
        #pragma unroll
        for (int kk = 0; kk < 4; kk++) {
            const float ek = (kk == 0) ? e_q.x : (kk == 1) ? e_q.y : (kk == 2) ? e_q.z : e_q.w;
            const ull e2 = pack2(ek, ek);
            const ull* w = W2 + (q * 4 + kk) * 32;
            #pragma unroll
            for (int j = 0; j < 32; j++) acc[j] = fma2(e2, w[j], acc[j]);
        }
    }

    float4* pre4 = ((float4*)g_z) + (size_t)t * 16;
    #pragma unroll
    for (int q = 0; q < 16; q++) {
        const float2 a0 = unpack2(acc[2 * q]);
        const float2 a1 = unpack2(acc[2 * q + 1]);
        pre4[q] = make_float4(a0.x, a0.y, a1.x, a1.y);
    }
}

// ---------- edge gather kernel: 8 THREADS PER EDGE (all accesses row-clustered) ----------
// warp = 4 edges x 8 channel-lanes; lane g owns channels 8g..8g+7 (2 float4 quads).
// WRST 1 (l<3): z = a*enorm written in place over pre; fused BN stats
// WRST 0 (l=3): no z write, no stats
template<int WRST>
__global__ void __launch_bounds__(256) k_edge_gt(
        const int* __restrict__ src, const int* __restrict__ dst,
        const float* __restrict__ enorm) {
    __shared__ float sSum[64], sSq[64];
    const int tid = threadIdx.x;
    if (WRST && tid < 64) { sSum[tid] = 0.f; sSq[tid] = 0.f; }
    if (WRST) __syncthreads();

    const int g = tid & 7;                       // channel-group lane
    const int edge = blockIdx.x * 32 + (tid >> 3);
    const int s = src[edge], d = dst[edge];
    const float zn = enorm[edge];
    const size_t eb = (size_t)edge * 16 + 2 * g; // float4 index of this thread's 8 channels

    float4* pre4 = (float4*)g_z;
    const float4 p0 = pre4[eb],     p1 = pre4[eb + 1];
    const float4 D0 = ((const float4*)g_Dh)[(size_t)s * 16 + 2 * g];
    const float4 D1 = ((const float4*)g_Dh)[(size_t)s * 16 + 2 * g + 1];
    const float4 E0 = ((const float4*)g_Eh)[(size_t)d * 16 + 2 * g];
    const float4 E1 = ((const float4*)g_Eh)[(size_t)d * 16 + 2 * g + 1];

    float a[8];
    a[0] = p0.x + D0.x + E0.x; a[1] = p0.y + D0.y + E0.y;
    a[2] = p0.z + D0.z + E0.z; a[3] = p0.w + D0.w + E0.w;
    a[4] = p1.x + D1.x + E1.x; a[5] = p1.y + D1.y + E1.y;
    a[6] = p1.z + D1.z + E1.z; a[7] = p1.w + D1.w + E1.w;

    float sg[8];
    #pragma unroll
    for (int i = 0; i < 8; i++) sg[i] = sigmoidf_fast(a[i]);

    if (WRST) {
        float z[8], qq[8];
        #pragma unroll
        for (int i = 0; i < 8; i++) { z[i] = a[i] * zn; qq[i] = z[i] * z[i]; }
        pre4[eb]     = make_float4(z[0], z[1], z[2], z[3]);
        pre4[eb + 1] = make_float4(z[4], z[5], z[6], z[7]);
        // butterfly over the 4 edges in this warp (lanes xor 8, 16)
        #pragma unroll
        for (int off = 8; off <= 16; off <<= 1) {
            #pragma unroll
            for (int i = 0; i < 8; i++) {
                z[i]  += __shfl_xor_sync(0xffffffffu, z[i], off);
                qq[i] += __shfl_xor_sync(0xffffffffu, qq[i], off);
            }
        }
        if ((tid & 31) < 8) {
            #pragma unroll
            for (int i = 0; i < 8; i++) {
                atomicAdd(&sSum[g * 8 + i], z[i]);
                atomicAdd(&sSq [g * 8 + i], qq[i]);
            }
        }
    }

    // gated aggregation atomics (4 dst rows per warp, contiguous within row)
    {
        const float4 B0 = ((const float4*)g_Bh)[(size_t)s * 16 + 2 * g];
        const float4 B1 = ((const float4*)g_Bh)[(size_t)s * 16 + 2 * g + 1];
        atomicAdd(((float4*)g_num) + (size_t)d * 16 + 2 * g,
                  make_float4(sg[0] * B0.x, sg[1] * B0.y, sg[2] * B0.z, sg[3] * B0.w));
        atomicAdd(((float4*)g_num) + (size_t)d * 16 + 2 * g + 1,
                  make_float4(sg[4] * B1.x, sg[5] * B1.y, sg[6] * B1.z, sg[7] * B1.w));
        atomicAdd(((float4*)g_den) + (size_t)d * 16 + 2 * g,
                  make_float4(sg[0], sg[1], sg[2], sg[3]));
        atomicAdd(((float4*)g_den) + (size_t)d * 16 + 2 * g + 1,
                  make_float4(sg[4], sg[5], sg[6], sg[7]));
    }

    if (WRST) {
        __syncthreads();
        if (tid < 64)
            atomicAdd(&g_statsP[blockIdx.x & 31][tid], (double)sSum[tid]);
        else if (tid < 128)
            atomicAdd(&g_statsP[blockIdx.x & 31][tid], (double)sSq[tid - 64]);
    }
}

// ---------- streaming edge update (full-BW pass): e_out = base + relu(BN(z)) ----------
// FIRST=1 (l=0): base = embed(ef)
template<int FIRST>
__global__ void __launch_bounds__(256) k_edge_C(
        const float* __restrict__ ef,
        const float* __restrict__ We_, const float* __restrict__ be_,
        const float* __restrict__ gam, const float* __restrict__ bet) {
    const size_t i = (size_t)blockIdx.x * 256 + threadIdx.x;   // quad idx, Ee*16 exact
    if (i >= (size_t)Ee * 16) return;
    const int q = (int)(i & 15);
    const float4 zv = ((const float4*)g_z)[i];
    float4 base;
    if (FIRST) {
        const float f = ef[i >> 4];
        const float4 w = ((const float4*)We_)[q];
        const float4 b = ((const float4*)be_)[q];
        base = make_float4(fmaf(f, w.x, b.x), fmaf(f, w.y, b.y),
                           fmaf(f, w.z, b.z), fmaf(f, w.w, b.w));
    } else {
        base = ((const float4*)g_e)[i];
    }
    const float4 g4 = ((const float4*)gam)[q];
    const float4 b4 = ((const float4*)bet)[q];
    const float4 mu = ((const float4*)g_bnp)[q];
    const float4 iv = ((const float4*)(g_bnp + 64))[q];
    base.x += fmaxf(0.f, g4.x * (zv.x - mu.x) * iv.x + b4.x);
    base.y += fmaxf(0.f, g4.y * (zv.y - mu.y) * iv.y + b4.y);
    base.z += fmaxf(0.f, g4.z * (zv.z - mu.z) * iv.z + b4.z);
    base.w += fmaxf(0.f, g4.w * (zv.w - mu.w) * iv.w + b4.w);
    ((float4*)g_e)[i] = base;
}

// ---------- node aggregate + graph norm + BN stats over hn ----------
__global__ void __launch_bounds__(256) k_node_B(const float* __restrict__ nnorm) {
    const int c = threadIdx.x & 63;
    const int slot = threadIdx.x >> 6;
    double s = 0.0, q = 0.0;
    for (int n = blockIdx.x * 4 + slot; n < Nn; n += gridDim.x * 4) {
        const size_t idx = (size_t)n * 64 + c;
        const float v = (g_Ah[idx] + g_num[idx] / (g_den[idx] + 1e-6f)) * nnorm[n];
        g_hn[idx] = v;
        s += v;
        q += (double)v * (double)v;
    }
    __shared__ double sh[512];
    sh[threadIdx.x] = s;
    sh[256 + threadIdx.x] = q;
    __syncthreads();
    if (threadIdx.x < 64) {
        s = sh[c] + sh[c + 64] + sh[c + 128] + sh[c + 192];
        q = sh[256 + c] + sh[256 + c + 64] + sh[256 + c + 128] + sh[256 + c + 192];
        const int st = blockIdx.x & 31;
        atomicAdd(&g_statsP[st][128 + c], s);
        atomicAdd(&g_statsP[st][192 + c], q);
    }
}

__global__ void k_finalize() {
    const int c = threadIdx.x;  // 64 threads
    double se = 0.0, qe = 0.0, sh2 = 0.0, qh = 0.0;
    #pragma unroll 4
    for (int st = 0; st < 32; st++) {
        se  += g_statsP[st][c];
        qe  += g_statsP[st][64 + c];
        sh2 += g_statsP[st][128 + c];
        qh  += g_statsP[st][192 + c];
    }
    const double mu_e = se / (double)Ee;
    const double var_e = qe / (double)Ee - mu_e * mu_e;
    g_bnp[c] = (float)mu_e;
    g_bnp[64 + c] = (float)(1.0 / sqrt(var_e + 1e-5));
    const double mu_h = sh2 / (double)Nn;
    const double var_h = qh / (double)Nn - mu_h * mu_h;
    g_bnp[128 + c] = (float)mu_h;
    g_bnp[192 + c] = (float)(1.0 / sqrt(var_h + 1e-5));
}

// ---------- node residual update: h += relu(BN(hn)) ----------
__global__ void __launch_bounds__(256) k_node_C(const float* __restrict__ gam,
                                                const float* __restrict__ bet) {
    const int i = blockIdx.x * 256 + threadIdx.x;
    if (i >= Nn * 16) return;
    const int q = i & 15;
    float4 hv = ((float4*)g_h)[i];
    const float4 hn = ((float4*)g_hn)[i];
    const float4 g4 = ((const float4*)gam)[q];
    const float4 b4 = ((const float4*)bet)[q];
    const float4 mu = ((const float4*)(g_bnp + 128))[q];
    const float4 iv = ((const float4*)(g_bnp + 192))[q];
    hv.x += fmaxf(0.f, g4.x * (hn.x - mu.x) * iv.x + b4.x);
    hv.y += fmaxf(0.f, g4.y * (hn.y - mu.y) * iv.y + b4.y);
    hv.z += fmaxf(0.f, g4.z * (hn.z - mu.z) * iv.z + b4.z);
    hv.w += fmaxf(0.f, g4.w * (hn.w - mu.w) * iv.w + b4.w);
    ((float4*)g_h)[i] = hv;
}

// ---------- readout (fused last-layer node BN+residual) ----------
__global__ void k_zero_out(float* __restrict__ out) {
    const int i = blockIdx.x * 256 + threadIdx.x;   // 128 blocks -> 32768 exact
    out[i] = 0.f;
    if (i < Gg) g_cnt[i] = 0.f;
}

__global__ void __launch_bounds__(256) k_readout(const int* __restrict__ gid,
                                                 const float* __restrict__ gamH,
                                                 const float* __restrict__ betH,
                                                 float* __restrict__ out) {
    const int i = blockIdx.x * 256 + threadIdx.x;   // exact: Nn*16 = 800000
    const int q = i & 15, n = i >> 4;
    float4 hv = ((const float4*)g_h)[i];
    const float4 hn = ((const float4*)g_hn)[i];
    const float4 g4 = ((const float4*)gamH)[q];
    const float4 b4 = ((const float4*)betH)[q];
    const float4 mu = ((const float4*)(g_bnp + 128))[q];
    const float4 iv = ((const float4*)(g_bnp + 192))[q];
    hv.x += fmaxf(0.f, g4.x * (hn.x - mu.x) * iv.x + b4.x);
    hv.y += fmaxf(0.f, g4.y * (hn.y - mu.y) * iv.y + b4.y);
    hv.z += fmaxf(0.f, g4.z * (hn.z - mu.z) * iv.z + b4.z);
    hv.w += fmaxf(0.f, g4.w * (hn.w - mu.w) * iv.w + b4.w);
    const int g = gid[n];
    atomicAdd(((float4*)out) + (size_t)g * 16 + q, hv);
    if (q == 0) atomicAdd(&g_cnt[g], 1.0f);
}

__global__ void k_div(float* __restrict__ out) {
    const int i = blockIdx.x * 256 + threadIdx.x;   // exact 32768
    out[i] /= fmaxf(g_cnt[i >> 6], 1.0f);
}

// =====================================================================
extern "C" void kernel_launch(void* const* d_in, const int* in_sizes, int n_in,
                              void* d_out, int out_size) {
    const float* nodes_feat = (const float*)d_in[0];
    const float* edges_feat = (const float*)d_in[1];
    const float* nnorm      = (const float*)d_in[2];
    const float* enorm      = (const float*)d_in[3];
    const float* W_h        = (const float*)d_in[4];
    const float* b_h        = (const float*)d_in[5];
    const float* W_e        = (const float*)d_in[6];
    const float* b_e        = (const float*)d_in[7];
    const float* Wa         = (const float*)d_in[8];
    const float* ba         = (const float*)d_in[9];
    const float* Wb         = (const float*)d_in[10];
    const float* bb         = (const float*)d_in[11];
    const float* Wc         = (const float*)d_in[12];
    const float* bc         = (const float*)d_in[13];
    const float* Wd         = (const float*)d_in[14];
    const float* bd         = (const float*)d_in[15];
    const float* We         = (const float*)d_in[16];
    const float* be         = (const float*)d_in[17];
    const float* gamma_h    = (const float*)d_in[18];
    const float* beta_h     = (const float*)d_in[19];
    const float* gamma_e    = (const float*)d_in[20];
    const float* beta_e     = (const float*)d_in[21];
    const int*   esrc       = (const int*)d_in[22];
    const int*   edst       = (const int*)d_in[23];
    const int*   gid        = (const int*)d_in[24];
    float* out = (float*)d_out;

    const int dynSmem = 4 * 4096 * 4 + 64 * 64 * 4;   // 81920 bytes
    cudaFuncSetAttribute(k_node_gemm, cudaFuncAttributeMaxDynamicSharedMemorySize, dynSmem);

    // all four Wc layers into constant memory (one 64 KB D2D copy)
    cudaMemcpyToSymbolAsync(cWc, Wc, 4 * 4096 * sizeof(float), 0,
                            cudaMemcpyDeviceToDevice, 0);                   // 1
    k_embed_h<<<(Nn + 63) / 64, 256>>>(nodes_feat, W_h, b_h);               // 2
    k_zero_out<<<128, 256>>>(out);                                          // 3

    const int NG = (Nn + 255) / 256;   // 196 blocks (256 nodes/block)
    const int EG = Ee / 256;           // 3125 blocks (mv: thread-per-edge)
    const int GG = Ee / 32;            // 25000 blocks (gt: 8 threads/edge)
    const int EC = (int)(((size_t)Ee * 16 + 255) / 256);
    for (int l = 0; l < 4; l++) {
        k_node_gemm<<<NG, 256, dynSmem>>>(
            Wa + (size_t)l * 4096, Wb + (size_t)l * 4096,
            Wd + (size_t)l * 4096, We + (size_t)l * 4096,
            ba + l * 64, bb + l * 64, bd + l * 64, be + l * 64);            // 4 (l=0)

        const float* bcL = bc + l * 64;
        if (l == 0)
            k_edge_mv<0><<<EG, 256>>>(l, bcL, edges_feat, W_e, b_e);        // 5 <- profiled
        else
            k_edge_mv<1><<<EG, 256>>>(l, bcL, edges_feat, W_e, b_e);

        if (l < 3)
            k_edge_gt<1><<<GG, 256>>>(esrc, edst, enorm);
        else
            k_edge_gt<0><<<GG, 256>>>(esrc, edst, enorm);

        k_node_B<<<1024, 256>>>(nnorm);
        k_finalize<<<1, 64>>>();
        if (l < 3) {
            k_node_C<<<(Nn * 16 + 255) / 256, 256>>>(gamma_h + l * 64, beta_h + l * 64);
            if (l == 0)
                k_edge_C<1><<<EC, 256>>>(edges_feat, W_e, b_e,
                                         gamma_e + l * 64, beta_e + l * 64);
            else
                k_edge_C<0><<<EC, 256>>>(edges_feat, W_e, b_e,
                                         gamma_e + l * 64, beta_e + l * 64);
        }
    }

    k_readout<<<Nn * 16 / 256, 256>>>(gid, gamma_h + 3 * 64, beta_h + 3 * 64, out);
    k_div<<<Gg * 64 / 256, 256>>>(out);
}

// round 14
// speedup vs baseline: 1.4330x; 1.0602x over previous
#include <cuda_runtime.h>

// Problem constants (fixed by the dataset)
#define Nn   50000
#define Ee   800000
#define Gg   512
#define DINc 128

typedef unsigned long long ull;

// ---------- f32x2 packed-FMA helpers (sm_103a) ----------
__device__ __forceinline__ ull fma2(ull a, ull b, ull c) {
    ull d;
    asm("fma.rn.f32x2 %0, %1, %2, %3;" : "=l"(d) : "l"(a), "l"(b), "l"(c));
    return d;
}
__device__ __forceinline__ ull pack2(float x, float y) {
    ull r;
    asm("mov.b64 %0, {%1,%2};" : "=l"(r) : "f"(x), "f"(y));
    return r;
}
__device__ __forceinline__ float2 unpack2(ull v) {
    float2 r;
    asm("mov.b64 {%0,%1}, %2;" : "=f"(r.x), "=f"(r.y) : "l"(v));
    return r;
}
__device__ __forceinline__ float sigmoidf_fast(float x) {
    return __fdividef(1.0f, 1.0f + __expf(-x));
}

// ALL FOUR per-layer edge weight matrices in constant memory (exactly 64 KB).
__constant__ float cWc[4][4096];

// ---------- scratch (static device globals; row-major e/z) ----------
__device__ float  g_h [(size_t)Nn * 64];
__device__ float  g_e [(size_t)Ee * 64];
__device__ float  g_z [(size_t)Ee * 64];   // holds z_{l-1} (in), then pre_l (out of mv), then z_l (out of gt)
__device__ float  g_Ah[(size_t)Nn * 64];
__device__ float  g_Bh[(size_t)Nn * 64];
__device__ float  g_Dh[(size_t)Nn * 64];
__device__ float  g_Eh[(size_t)Nn * 64];
__device__ float  g_num[(size_t)Nn * 64];
__device__ float  g_den[(size_t)Nn * 64];
__device__ float  g_hn[(size_t)Nn * 64];
__device__ double g_statsP[32][256];   // striped: [0:64) e_sum [64:128) e_sq [128:192) h_sum [192:256) h_sq
__device__ __align__(16) float g_bnp[256];  // [0:64) mu_e [64:128) inv_e [128:192) mu_h [192:256) inv_h
__device__ float  g_cnt[Gg];

// ---------- initial node embedding: h = nodes_feat @ W_h + b_h ----------
__global__ void __launch_bounds__(256) k_embed_h(const float* __restrict__ x,
                                                 const float* __restrict__ W,
                                                 const float* __restrict__ b) {
    __shared__ __align__(16) float sW[DINc][64];
    __shared__ __align__(16) float sx[16][DINc];
    const int t = threadIdx.x;
    for (int i = t; i < DINc * 64 / 4; i += 256)
        ((float4*)&sW[0][0])[i] = ((const float4*)W)[i];

    const int cq = t & 15, m = t >> 4;
    const float4 bias = ((const float4*)b)[cq];
    const int base = blockIdx.x * 64;

    for (int it = 0; it < 4; it++) {
        const int n0 = base + it * 16;
        __syncthreads();
        for (int i = t; i < 16 * DINc / 4; i += 256) {
            const int row = i >> 5, c4 = i & 31;
            const int n = n0 + row;
            float4 v = make_float4(0.f, 0.f, 0.f, 0.f);
            if (n < Nn) v = ((const float4*)x)[(size_t)n * 32 + c4];
            ((float4*)&sx[row][0])[c4] = v;
        }
        __syncthreads();
        float4 acc = bias;
        #pragma unroll 8
        for (int k = 0; k < DINc; k++) {
            const float xv = sx[m][k];
            const float4 w = ((const float4*)&sW[k][0])[cq];
            acc.x += xv * w.x; acc.y += xv * w.y;
            acc.z += xv * w.z; acc.w += xv * w.w;
        }
        const int n = n0 + m;
        if (n < Nn) ((float4*)g_h)[(size_t)n * 16 + cq] = acc;
    }
}

// ---------- per-layer node GEMMs v3: 4 nodes/thread, f32x2 FMA, 128-bit LDS ----------
extern __shared__ float dsm[];
__global__ void __launch_bounds__(256, 2) k_node_gemm(
        const float* __restrict__ Wa, const float* __restrict__ Wb,
        const float* __restrict__ Wd, const float* __restrict__ We_,
        const float* __restrict__ ba_, const float* __restrict__ bb_,
        const float* __restrict__ bd_, const float* __restrict__ be_) {
    float* sW = dsm;              // 4 * 4096 floats
    float* sx = dsm + 4 * 4096;   // 64 * 64 floats
    const int t = threadIdx.x;

    if (blockIdx.x == 0) {        // zero striped BN stats for this layer
        double* p = &g_statsP[0][0];
        for (int i = t; i < 32 * 256; i += 256) p[i] = 0.0;
    }

    for (int i = t; i < 1024; i += 256) ((float4*)(sW + 0 * 4096))[i] = ((const float4*)Wa)[i];
    for (int i = t; i < 1024; i += 256) ((float4*)(sW + 1 * 4096))[i] = ((const float4*)Wb)[i];
    for (int i = t; i < 1024; i += 256) ((float4*)(sW + 2 * 4096))[i] = ((const float4*)Wd)[i];
    for (int i = t; i < 1024; i += 256) ((float4*)(sW + 3 * 4096))[i] = ((const float4*)We_)[i];

    const int cq = t & 15, m = t >> 4;   // thread: nodes 4m..4m+3 of the tile, channels 4cq..4cq+3
    const float4 bA = ((const float4*)ba_)[cq];
    const float4 bB = ((const float4*)bb_)[cq];
    const float4 bD = ((const float4*)bd_)[cq];
    const float4 bE = ((const float4*)be_)[cq];
    const ull bA0 = pack2(bA.x, bA.y), bA1 = pack2(bA.z, bA.w);
    const ull bB0 = pack2(bB.x, bB.y), bB1 = pack2(bB.z, bB.w);
    const ull bD0 = pack2(bD.x, bD.y), bD1 = pack2(bD.z, bD.w);
    const ull bE0 = pack2(bE.x, bE.y), bE1 = pack2(bE.z, bE.w);
    const int base = blockIdx.x * 256;

    for (int it = 0; it < 4; it++) {
        const int n0 = base + it * 64;
        __syncthreads();
        #pragma unroll
        for (int i = t; i < 1024; i += 256) {   // 64 rows x 16 quads
            const int row = i >> 4, c4 = i & 15;
            const int n = n0 + row;
            float4 v = make_float4(0.f, 0.f, 0.f, 0.f);
            if (n < Nn) v = ((const float4*)g_h)[(size_t)n * 16 + c4];
            ((float4*)sx)[row * 16 + c4] = v;
        }
        __syncthreads();
        ull aA[8], aB[8], aD[8], aE[8];   // 4 nodes x 2 channel-pairs
        #pragma unroll
        for (int r = 0; r < 4; r++) {
            aA[2 * r] = bA0; aA[2 * r + 1] = bA1;
            aB[2 * r] = bB0; aB[2 * r + 1] = bB1;
            aD[2 * r] = bD0; aD[2 * r + 1] = bD1;
            aE[2 * r] = bE0; aE[2 * r + 1] = bE1;
        }
        #pragma unroll 4
        for (int k = 0; k < 64; k++) {
            ull x[4];
            #pragma unroll
            for (int r = 0; r < 4; r++) {
                const float xv = sx[(4 * m + r) * 64 + k];
                x[r] = pack2(xv, xv);
            }
            const ulonglong2 wA = ((const ulonglong2*)(sW + 0 * 4096 + k * 64))[cq];
            const ulonglong2 wB = ((const ulonglong2*)(sW + 1 * 4096 + k * 64))[cq];
            const ulonglong2 wD = ((const ulonglong2*)(sW + 2 * 4096 + k * 64))[cq];
            const ulonglong2 wE = ((const ulonglong2*)(sW + 3 * 4096 + k * 64))[cq];
            #pragma unroll
            for (int r = 0; r < 4; r++) {
                aA[2 * r] = fma2(x[r], wA.x, aA[2 * r]);
                aA[2 * r + 1] = fma2(x[r], wA.y, aA[2 * r + 1]);
                aB[2 * r] = fma2(x[r], wB.x, aB[2 * r]);
                aB[2 * r + 1] = fma2(x[r], wB.y, aB[2 * r + 1]);
                aD[2 * r] = fma2(x[r], wD.x, aD[2 * r]);
                aD[2 * r + 1] = fma2(x[r], wD.y, aD[2 * r + 1]);
                aE[2 * r] = fma2(x[r], wE.x, aE[2 * r]);
                aE[2 * r + 1] = fma2(x[r], wE.y, aE[2 * r + 1]);
            }
        }
        #pragma unroll
        for (int r = 0; r < 4; r++) {
            const int n = n0 + 4 * m + r;
            if (n < Nn) {
                const size_t o = (size_t)n * 16 + cq;
                float2 p0, p1;
                p0 = unpack2(aA[2 * r]); p1 = unpack2(aA[2 * r + 1]);
                ((float4*)g_Ah)[o] = make_float4(p0.x, p0.y, p1.x, p1.y);
                p0 = unpack2(aB[2 * r]); p1 = unpack2(aB[2 * r + 1]);
                ((float4*)g_Bh)[o] = make_float4(p0.x, p0.y, p1.x, p1.y);
                p0 = unpack2(aD[2 * r]); p1 = unpack2(aD[2 * r + 1]);
                ((float4*)g_Dh)[o] = make_float4(p0.x, p0.y, p1.x, p1.y);
                p0 = unpack2(aE[2 * r]); p1 = unpack2(aE[2 * r + 1]);
                ((float4*)g_Eh)[o] = make_float4(p0.x, p0.y, p1.x, p1.y);
                ((float4*)g_num)[o] = make_float4(0.f, 0.f, 0.f, 0.f);
                ((float4*)g_den)[o] = make_float4(0.f, 0.f, 0.f, 0.f);
            }
        }
    }
}

// ---------- edge matvec kernel (STREAMING) with fused edge BN+residual of prev layer ----------
// MODE 0 (l=0): e = embed(ef);                 no e write
// MODE 1 (l=1): e = embed(ef) + relu(BN(z0));  write e
// MODE 2 (l=2): e = g_e + relu(BN(z1));        write e
// MODE 3 (l=3): e = g_e + relu(BN(z2));        no e write
// All modes: pre = e@Wc + bc -> g_z (overwrites z_prev in place)
template<int MODE>
__global__ void __launch_bounds__(256) k_edge_mv(
        int layer,
        const float* __restrict__ bc_l,
        const float* __restrict__ ef,
        const float* __restrict__ We_, const float* __restrict__ be_,
        const float* __restrict__ gamE, const float* __restrict__ betE) {
    const int t = blockIdx.x * 256 + threadIdx.x;   // edge id (800000 % 256 == 0)

    ull acc[32];
    #pragma unroll
    for (int q = 0; q < 16; q++) {
        const float4 bv = ((const float4*)bc_l)[q];
        acc[2 * q]     = pack2(bv.x, bv.y);
        acc[2 * q + 1] = pack2(bv.z, bv.w);
    }

    const float f = (MODE <= 1) ? ef[t] : 0.f;
    float4* e4 = ((float4*)g_e) + (size_t)t * 16;
    float4* z4 = ((float4*)g_z) + (size_t)t * 16;
    const ulonglong2* W2 = (const ulonglong2*)cWc[layer];  // warp-uniform LDCU.128

    #pragma unroll 2
    for (int q = 0; q < 16; q++) {
        float4 e_q;
        if (MODE <= 1) {
            const float4 w = ((const float4*)We_)[q];
            const float4 b = ((const float4*)be_)[q];
            e_q = make_float4(fmaf(f, w.x, b.x), fmaf(f, w.y, b.y),
                              fmaf(f, w.z, b.z), fmaf(f, w.w, b.w));
        } else {
            e_q = e4[q];
        }
        if (MODE >= 1) {   // e += relu(BN_{l-1}(z_{l-1}))
            const float4 zq = z4[q];
            const float4 ga = ((const float4*)gamE)[q];
            const float4 bt = ((const float4*)betE)[q];
            const float4 mu = ((const float4*)g_bnp)[q];
            const float4 iv = ((const float4*)(g_bnp + 64))[q];
            e_q.x += fmaxf(0.f, ga.x * (zq.x - mu.x) * iv.x + bt.x);
            e_q.y += fmaxf(0.f, ga.y * (zq.y - mu.y) * iv.y + bt.y);
            e_q.z += fmaxf(0.f, ga.z * (zq.z - mu.z) * iv.z + bt.z);
            e_q.w += fmaxf(0.f, ga.w * (zq.w - mu.w) * iv.w + bt.w);
            if (MODE == 1 || MODE == 2) e4[q] = e_q;   // persist e for next layer
        }
        #pragma unroll
        for (int kk = 0; kk < 4; kk++) {
            const float ek = (kk == 0) ? e_q.x : (kk == 1) ? e_q.y : (kk == 2) ? e_q.z : e_q.w;
            const ull e2 = pack2(ek, ek);
            const ulonglong2* w = W2 + (q * 4 + kk) * 16;
            #pragma unroll
            for (int j = 0; j < 16; j++) {
                const ulonglong2 wv = w[j];
                acc[2 * j]     = fma2(e2, wv.x, acc[2 * j]);
                acc[2 * j + 1] = fma2(e2, wv.y, acc[2 * j + 1]);
            }
        }
    }

    #pragma unroll
    for (int q = 0; q < 16; q++) {
        const float2 a0 = unpack2(acc[2 * q]);
        const float2 a1 = unpack2(acc[2 * q + 1]);
        z4[q] = make_float4(a0.x, a0.y, a1.x, a1.y);   // pre overwrites z_prev
    }
}

// ---------- edge gather kernel: 8 THREADS PER EDGE ----------
// WRST 1 (l<3): z = a*enorm written in place over pre; fused BN stats
// WRST 0 (l=3): no z write, no stats
template<int WRST>
__global__ void __launch_bounds__(256) k_edge_gt(
        const int* __restrict__ src, const int* __restrict__ dst,
        const float* __restrict__ enorm) {
    __shared__ float sSum[64], sSq[64];
    const int tid = threadIdx.x;
    if (WRST && tid < 64) { sSum[tid] = 0.f; sSq[tid] = 0.f; }
    if (WRST) __syncthreads();

    const int g = tid & 7;                       // channel-group lane
    const int edge = blockIdx.x * 32 + (tid >> 3);
    const int s = src[edge], d = dst[edge];
    const float zn = enorm[edge];
    const size_t eb = (size_t)edge * 16 + 2 * g; // float4 index of this thread's 8 channels

    float4* pre4 = (float4*)g_z;
    const float4 p0 = pre4[eb],     p1 = pre4[eb + 1];
    const float4 D0 = ((const float4*)g_Dh)[(size_t)s * 16 + 2 * g];
    const float4 D1 = ((const float4*)g_Dh)[(size_t)s * 16 + 2 * g + 1];
    const float4 E0 = ((const float4*)g_Eh)[(size_t)d * 16 + 2 * g];
    const float4 E1 = ((const float4*)g_Eh)[(size_t)d * 16 + 2 * g + 1];

    float a[8];
    a[0] = p0.x + D0.x + E0.x; a[1] = p0.y + D0.y + E0.y;
    a[2] = p0.z + D0.z + E0.z; a[3] = p0.w + D0.w + E0.w;
    a[4] = p1.x + D1.x + E1.x; a[5] = p1.y + D1.y + E1.y;
    a[6] = p1.z + D1.z + E1.z; a[7] = p1.w + D1.w + E1.w;

    float sg[8];
    #pragma unroll
    for (int i = 0; i < 8; i++) sg[i] = sigmoidf_fast(a[i]);

    if (WRST) {
        float z[8], qq[8];
        #pragma unroll
        for (int i = 0; i < 8; i++) { z[i] = a[i] * zn; qq[i] = z[i] * z[i]; }
        pre4[eb]     = make_float4(z[0], z[1], z[2], z[3]);
        pre4[eb + 1] = make_float4(z[4], z[5], z[6], z[7]);
        #pragma unroll
        for (int off = 8; off <= 16; off <<= 1) {
            #pragma unroll
            for (int i = 0; i < 8; i++) {
                z[i]  += __shfl_xor_sync(0xffffffffu, z[i], off);
                qq[i] += __shfl_xor_sync(0xffffffffu, qq[i], off);
            }
        }
        if ((tid & 31) < 8) {
            #pragma unroll
            for (int i = 0; i < 8; i++) {
                atomicAdd(&sSum[g * 8 + i], z[i]);
                atomicAdd(&sSq [g * 8 + i], qq[i]);
            }
        }
    }

    // gated aggregation atomics (4 dst rows per warp, contiguous within row)
    {
        const float4 B0 = ((const float4*)g_Bh)[(size_t)s * 16 + 2 * g];
        const float4 B1 = ((const float4*)g_Bh)[(size_t)s * 16 + 2 * g + 1];
        atomicAdd(((float4*)g_num) + (size_t)d * 16 + 2 * g,
                  make_float4(sg[0] * B0.x, sg[1] * B0.y, sg[2] * B0.z, sg[3] * B0.w));
        atomicAdd(((float4*)g_num) + (size_t)d * 16 + 2 * g + 1,
                  make_float4(sg[4] * B1.x, sg[5] * B1.y, sg[6] * B1.z, sg[7] * B1.w));
        atomicAdd(((float4*)g_den) + (size_t)d * 16 + 2 * g,
                  make_float4(sg[0], sg[1], sg[2], sg[3]));
        atomicAdd(((float4*)g_den) + (size_t)d * 16 + 2 * g + 1,
                  make_float4(sg[4], sg[5], sg[6], sg[7]));
    }

    if (WRST) {
        __syncthreads();
        if (tid < 64)
            atomicAdd(&g_statsP[blockIdx.x & 31][tid], (double)sSum[tid]);
        else if (tid < 128)
            atomicAdd(&g_statsP[blockIdx.x & 31][tid], (double)sSq[tid - 64]);
    }
}

// ---------- node aggregate + graph norm + BN stats over hn ----------
__global__ void __launch_bounds__(256) k_node_B(const float* __restrict__ nnorm) {
    const int c = threadIdx.x & 63;
    const int slot = threadIdx.x >> 6;
    double s = 0.0, q = 0.0;
    for (int n = blockIdx.x * 4 + slot; n < Nn; n += gridDim.x * 4) {
        const size_t idx = (size_t)n * 64 + c;
        const float v = (g_Ah[idx] + g_num[idx] / (g_den[idx] + 1e-6f)) * nnorm[n];
        g_hn[idx] = v;
        s += v;
        q += (double)v * (double)v;
    }
    __shared__ double sh[512];
    sh[threadIdx.x] = s;
    sh[256 + threadIdx.x] = q;
    __syncthreads();
    if (threadIdx.x < 64) {
        s = sh[c] + sh[c + 64] + sh[c + 128] + sh[c + 192];
        q = sh[256 + c] + sh[256 + c + 64] + sh[256 + c + 128] + sh[256 + c + 192];
        const int st = blockIdx.x & 31;
        atomicAdd(&g_statsP[st][128 + c], s);
        atomicAdd(&g_statsP[st][192 + c], q);
    }
}

__global__ void k_finalize() {
    const int c = threadIdx.x;  // 64 threads
    double se = 0.0, qe = 0.0, sh2 = 0.0, qh = 0.0;
    #pragma unroll 4
    for (int st = 0; st < 32; st++) {
        se  += g_statsP[st][c];
        qe  += g_statsP[st][64 + c];
        sh2 += g_statsP[st][128 + c];
        qh  += g_statsP[st][192 + c];
    }
    const double mu_e = se / (double)Ee;
    const double var_e = qe / (double)Ee - mu_e * mu_e;
    g_bnp[c] = (float)mu_e;
    g_bnp[64 + c] = (float)(1.0 / sqrt(var_e + 1e-5));
    const double mu_h = sh2 / (double)Nn;
    const double var_h = qh / (double)Nn - mu_h * mu_h;
    g_bnp[128 + c] = (float)mu_h;
    g_bnp[192 + c] = (float)(1.0 / sqrt(var_h + 1e-5));
}

// ---------- node residual update: h += relu(BN(hn)) ----------
__global__ void __launch_bounds__(256) k_node_C(const float* __restrict__ gam,
                                                const float* __restrict__ bet) {
    const int i = blockIdx.x * 256 + threadIdx.x;
    if (i >= Nn * 16) return;
    const int q = i & 15;
    float4 hv = ((float4*)g_h)[i];
    const float4 hn = ((float4*)g_hn)[i];
    const float4 g4 = ((const float4*)gam)[q];
    const float4 b4 = ((const float4*)bet)[q];
    const float4 mu = ((const float4*)(g_bnp + 128))[q];
    const float4 iv = ((const float4*)(g_bnp + 192))[q];
    hv.x += fmaxf(0.f, g4.x * (hn.x - mu.x) * iv.x + b4.x);
    hv.y += fmaxf(0.f, g4.y * (hn.y - mu.y) * iv.y + b4.y);
    hv.z += fmaxf(0.f, g4.z * (hn.z - mu.z) * iv.z + b4.z);
    hv.w += fmaxf(0.f, g4.w * (hn.w - mu.w) * iv.w + b4.w);
    ((float4*)g_h)[i] = hv;
}

// ---------- readout (fused last-layer node BN+residual) ----------
__global__ void k_zero_out(float* __restrict__ out) {
    const int i = blockIdx.x * 256 + threadIdx.x;   // 128 blocks -> 32768 exact
    out[i] = 0.f;
    if (i < Gg) g_cnt[i] = 0.f;
}

__global__ void __launch_bounds__(256) k_readout(const int* __restrict__ gid,
                                                 const float* __restrict__ gamH,
                                                 const float* __restrict__ betH,
                                                 float* __restrict__ out) {
    const int i = blockIdx.x * 256 + threadIdx.x;   // exact: Nn*16 = 800000
    const int q = i & 15, n = i >> 4;
    float4 hv = ((const float4*)g_h)[i];
    const float4 hn = ((const float4*)g_hn)[i];
    const float4 g4 = ((const float4*)gamH)[q];
    const float4 b4 = ((const float4*)betH)[q];
    const float4 mu = ((const float4*)(g_bnp + 128))[q];
    const float4 iv = ((const float4*)(g_bnp + 192))[q];
    hv.x += fmaxf(0.f, g4.x * (hn.x - mu.x) * iv.x + b4.x);
    hv.y += fmaxf(0.f, g4.y * (hn.y - mu.y) * iv.y + b4.y);
    hv.z += fmaxf(0.f, g4.z * (hn.z - mu.z) * iv.z + b4.z);
    hv.w += fmaxf(0.f, g4.w * (hn.w - mu.w) * iv.w + b4.w);
    const int g = gid[n];
    atomicAdd(((float4*)out) + (size_t)g * 16 + q, hv);
    if (q == 0) atomicAdd(&g_cnt[g], 1.0f);
}

__global__ void k_div(float* __restrict__ out) {
    const int i = blockIdx.x * 256 + threadIdx.x;   // exact 32768
    out[i] /= fmaxf(g_cnt[i >> 6], 1.0f);
}

// =====================================================================
extern "C" void kernel_launch(void* const* d_in, const int* in_sizes, int n_in,
                              void* d_out, int out_size) {
    const float* nodes_feat = (const float*)d_in[0];
    const float* edges_feat = (const float*)d_in[1];
    const float* nnorm      = (const float*)d_in[2];
    const float* enorm      = (const float*)d_in[3];
    const float* W_h        = (const float*)d_in[4];
    const float* b_h        = (const float*)d_in[5];
    const float* W_e        = (const float*)d_in[6];
    const float* b_e        = (const float*)d_in[7];
    const float* Wa         = (const float*)d_in[8];
    const float* ba         = (const float*)d_in[9];
    const float* Wb         = (const float*)d_in[10];
    const float* bb         = (const float*)d_in[11];
    const float* Wc         = (const float*)d_in[12];
    const float* bc         = (const float*)d_in[13];
    const float* Wd         = (const float*)d_in[14];
    const float* bd         = (const float*)d_in[15];
    const float* We         = (const float*)d_in[16];
    const float* be         = (const float*)d_in[17];
    const float* gamma_h    = (const float*)d_in[18];
    const float* beta_h     = (const float*)d_in[19];
    const float* gamma_e    = (const float*)d_in[20];
    const float* beta_e     = (const float*)d_in[21];
    const int*   esrc       = (const int*)d_in[22];
    const int*   edst       = (const int*)d_in[23];
    const int*   gid        = (const int*)d_in[24];
    float* out = (float*)d_out;

    const int dynSmem = 4 * 4096 * 4 + 64 * 64 * 4;   // 81920 bytes
    cudaFuncSetAttribute(k_node_gemm, cudaFuncAttributeMaxDynamicSharedMemorySize, dynSmem);

    // all four Wc layers into constant memory (one 64 KB D2D copy)
    cudaMemcpyToSymbolAsync(cWc, Wc, 4 * 4096 * sizeof(float), 0,
                            cudaMemcpyDeviceToDevice, 0);                   // 1
    k_embed_h<<<(Nn + 63) / 64, 256>>>(nodes_feat, W_h, b_h);               // 2
    k_zero_out<<<128, 256>>>(out);                                          // 3

    const int NG = (Nn + 255) / 256;   // 196 blocks (256 nodes/block)
    const int EG = Ee / 256;           // 3125 blocks (mv: thread-per-edge)
    const int GG = Ee / 32;            // 25000 blocks (gt: 8 threads/edge)
    for (int l = 0; l < 4; l++) {
        k_node_gemm<<<NG, 256, dynSmem>>>(
            Wa + (size_t)l * 4096, Wb + (size_t)l * 4096,
            Wd + (size_t)l * 4096, We + (size_t)l * 4096,
            ba + l * 64, bb + l * 64, bd + l * 64, be + l * 64);            // 4 (l=0)

        const float* bcL = bc + l * 64;
        const float* gE  = gamma_e + (l > 0 ? (l - 1) * 64 : 0);
        const float* bE  = beta_e  + (l > 0 ? (l - 1) * 64 : 0);
        switch (l) {
        case 0: k_edge_mv<0><<<EG, 256>>>(l, bcL, edges_feat, W_e, b_e, gE, bE); break; // 5 <- profiled
        case 1: k_edge_mv<1><<<EG, 256>>>(l, bcL, edges_feat, W_e, b_e, gE, bE); break;
        case 2: k_edge_mv<2><<<EG, 256>>>(l, bcL, edges_feat, W_e, b_e, gE, bE); break;
        case 3: k_edge_mv<3><<<EG, 256>>>(l, bcL, edges_feat, W_e, b_e, gE, bE); break;
        }

        if (l < 3)
            k_edge_gt<1><<<GG, 256>>>(esrc, edst, enorm);
        else
            k_edge_gt<0><<<GG, 256>>>(esrc, edst, enorm);

        k_node_B<<<1024, 256>>>(nnorm);
        k_finalize<<<1, 64>>>();
        if (l < 3)
            k_node_C<<<(Nn * 16 + 255) / 256, 256>>>(gamma_h + l * 64, beta_h + l * 64);
    }

    k_readout<<<Nn * 16 / 256, 256>>>(gid, gamma_h + 3 * 64, beta_h + 3 * 64, out);
    k_div<<<Gg * 64 / 256, 256>>>(out);
}